// round 13
// baseline (speedup 1.0000x reference)
#include <cuda_runtime.h>
#include <cstdint>

// Problem constants
#define TSTEPS 8192
#define MDIM   2048   // mem_dim
#define GDIM   8192   // 4*mem_dim
#define KDIM   2048   // in_dim

// Recurrence kernel config
#define NCTA   128            // grid CTAs (must be <= SM count; GB300 has 152)
#define NTH    512            // 16 warps; warp w owns hidden unit j = cta*16 + w
#define JPC    16             // MDIM / NCTA
#define SROWS  26             // gate-rows per CTA cached in smem (of 64); 26*8KB = 208KB
#define REC_SMEM ((MDIM + SROWS * MDIM) * sizeof(float))   // 221184 B

// Scratch (static __device__ arrays: the sanctioned no-alloc workaround)
__device__ float g_xproj[(size_t)TSTEPS * GDIM];   // 256 MB
__device__ float g_h[2][MDIM];                     // double-buffered hidden state
__device__ unsigned int          g_cnt;            // barrier arrival counter
__device__ volatile unsigned int g_gen;            // barrier generation (monotonic)

// ---------------------------------------------------------------------------
// Kernel A: x_proj[t][g] = sum_k inputs[t][k] * Wx[g][k] + bx[g] + bh[g]
// Classic 128x128x16 SGEMM, 256 threads, 8x8 register microtile.
// ---------------------------------------------------------------------------
#define BM 128
#define BN 128
#define BK 16
#define TM 8
#define TN 8

__global__ __launch_bounds__(256, 2)
void xproj_gemm(const float* __restrict__ A,    // inputs [T][K]
                const float* __restrict__ B,    // Wx     [G][K]
                const float* __restrict__ bx,
                const float* __restrict__ bh)
{
    __shared__ float As[BK][BM];
    __shared__ float Bs[BK][BN];

    const int tid = threadIdx.x;
    const int tx  = tid & 15;    // 0..15 -> N
    const int ty  = tid >> 4;    // 0..15 -> M

    const float* Ab = A + (size_t)blockIdx.y * BM * KDIM;
    const float* Bb = B + (size_t)blockIdx.x * BN * KDIM;

    float acc[TM][TN];
#pragma unroll
    for (int i = 0; i < TM; i++)
#pragma unroll
        for (int j = 0; j < TN; j++) acc[i][j] = 0.f;

    for (int k0 = 0; k0 < KDIM; k0 += BK) {
        // Load 128x16 tiles of A and B (K-contiguous), store K-major in smem.
#pragma unroll
        for (int r = 0; r < 2; r++) {
            int i   = tid + r * 256;     // 0..511 float4 slots
            int row = i >> 2;            // 0..127
            int kq  = (i & 3) * 4;       // 0,4,8,12
            float4 va = *(const float4*)(Ab + (size_t)row * KDIM + k0 + kq);
            As[kq + 0][row] = va.x; As[kq + 1][row] = va.y;
            As[kq + 2][row] = va.z; As[kq + 3][row] = va.w;
            float4 vb = *(const float4*)(Bb + (size_t)row * KDIM + k0 + kq);
            Bs[kq + 0][row] = vb.x; Bs[kq + 1][row] = vb.y;
            Bs[kq + 2][row] = vb.z; Bs[kq + 3][row] = vb.w;
        }
        __syncthreads();

#pragma unroll
        for (int kk = 0; kk < BK; kk++) {
            float ra[TM], rb[TN];
            const float4* pa = (const float4*)&As[kk][ty * TM];
            const float4* pb = (const float4*)&Bs[kk][tx * TN];
            float4 a0 = pa[0], a1 = pa[1];
            float4 b0 = pb[0], b1 = pb[1];
            ra[0] = a0.x; ra[1] = a0.y; ra[2] = a0.z; ra[3] = a0.w;
            ra[4] = a1.x; ra[5] = a1.y; ra[6] = a1.z; ra[7] = a1.w;
            rb[0] = b0.x; rb[1] = b0.y; rb[2] = b0.z; rb[3] = b0.w;
            rb[4] = b1.x; rb[5] = b1.y; rb[6] = b1.z; rb[7] = b1.w;
#pragma unroll
            for (int i = 0; i < TM; i++)
#pragma unroll
                for (int j = 0; j < TN; j++)
                    acc[i][j] = fmaf(ra[i], rb[j], acc[i][j]);
        }
        __syncthreads();
    }

    const int grow = blockIdx.y * BM + ty * TM;
    const int gcol = blockIdx.x * BN + tx * TN;
    float bias[TN];
#pragma unroll
    for (int j = 0; j < TN; j++) bias[j] = bx[gcol + j] + bh[gcol + j];

#pragma unroll
    for (int i = 0; i < TM; i++) {
        float4 o0, o1;
        o0.x = acc[i][0] + bias[0]; o0.y = acc[i][1] + bias[1];
        o0.z = acc[i][2] + bias[2]; o0.w = acc[i][3] + bias[3];
        o1.x = acc[i][4] + bias[4]; o1.y = acc[i][5] + bias[5];
        o1.z = acc[i][6] + bias[6]; o1.w = acc[i][7] + bias[7];
        float4* dst = (float4*)(g_xproj + (size_t)(grow + i) * GDIM + gcol);
        dst[0] = o0;
        dst[1] = o1;
    }
}

// ---------------------------------------------------------------------------
// Grid-wide barrier (all NCTA CTAs co-resident: 128 CTAs, 221KB smem -> 1/SM,
// GB300 has 152 SMs). Generation counter is monotonic -> no reset needed
// across graph replays; count self-resets each phase.
// ---------------------------------------------------------------------------
__device__ __forceinline__ void grid_bar()
{
    __syncthreads();
    if (threadIdx.x == 0) {
        unsigned gen = g_gen;           // must read BEFORE arriving
        __threadfence();
        unsigned arrived = atomicAdd(&g_cnt, 1);
        if (arrived == NCTA - 1) {
            g_cnt = 0;
            __threadfence();
            g_gen = gen + 1;            // release
        } else {
            while (g_gen == gen) { __nanosleep(64); }
        }
        __threadfence();                // acquire
    }
    __syncthreads();
}

// ---------------------------------------------------------------------------
// Kernel B: persistent LSTM recurrence.
// CTA c owns hidden units j in [c*16, c*16+16); warp w owns unit j = c*16+w
// and its 4 gate rows (i,o,f,u) of Wh. 26 of the CTA's 64 rows live in smem,
// the rest stream from L2 each step. c stays in lane-0 registers; h is
// broadcast through a double-buffered __device__ array with one grid barrier
// per timestep.
// ---------------------------------------------------------------------------
__global__ void __launch_bounds__(NTH, 1)
lstm_rec(const float* __restrict__ Wh, float* __restrict__ out)
{
    extern __shared__ float sm[];
    float* h_s = sm;                 // MDIM floats
    float* w_s = sm + MDIM;          // SROWS * MDIM floats

    const int tid  = threadIdx.x;
    const int lane = tid & 31;
    const int w    = tid >> 5;           // warp index 0..15 == local j
    const int cta  = blockIdx.x;
    const int j    = cta * JPC + w;      // global hidden unit

    // One-time: copy this CTA's smem-resident weight rows.
    // Local row l = gate*16 + j_local; rows l < SROWS are in smem.
    for (int l = 0; l < SROWS; l++) {
        int gate = l >> 4;
        int jl   = l & 15;
        size_t grow = (size_t)(gate * MDIM + cta * JPC + jl) * MDIM;
        ((float4*)(w_s + (size_t)l * MDIM))[tid] = ((const float4*)(Wh + grow))[tid];
    }

    // Per-gate weight-row pointers (smem or global, uniform per warp).
    const float* wp[4];
#pragma unroll
    for (int g = 0; g < 4; g++) {
        int l = g * 16 + w;
        if (l < SROWS) wp[g] = w_s + (size_t)l * MDIM;
        else           wp[g] = Wh + (size_t)(g * MDIM + j) * MDIM;
    }

    // Init: h0 = 0 (buffer 0), c0 = 0 in registers.
    if (lane == 0) g_h[0][j] = 0.f;
    float cval = 0.f, hval = 0.f;
    __threadfence();
    grid_bar();

    for (int t = 0; t < TSTEPS; t++) {
        // Snapshot h_prev (written by other CTAs -> bypass L1 with ld.cg).
        {
            float4 hv = __ldcg(((const float4*)g_h[t & 1]) + tid);
            ((float4*)h_s)[tid] = hv;
        }
        __syncthreads();

        // Prefetch this step's x_proj values early (independent of h).
        float xp0 = 0.f, xp1 = 0.f, xp2 = 0.f, xp3 = 0.f;
        if (lane == 0) {
            const float* xr = g_xproj + (size_t)t * GDIM + j;
            xp0 = __ldcs(xr);
            xp1 = __ldcs(xr + MDIM);
            xp2 = __ldcs(xr + 2 * MDIM);
            xp3 = __ldcs(xr + 3 * MDIM);
        }

        // 4 dot products of length 2048 (one per gate), warp-parallel over k.
        float a0 = 0.f, a1 = 0.f, a2 = 0.f, a3 = 0.f;
#pragma unroll
        for (int it = 0; it < MDIM / 128; it++) {
            int k0 = it * 128 + lane * 4;
            float4 h4 = *((const float4*)(h_s + k0));
            float4 w0 = *((const float4*)(wp[0] + k0));
            float4 w1 = *((const float4*)(wp[1] + k0));
            float4 w2 = *((const float4*)(wp[2] + k0));
            float4 w3 = *((const float4*)(wp[3] + k0));
            a0 = fmaf(h4.x, w0.x, a0); a0 = fmaf(h4.y, w0.y, a0);
            a0 = fmaf(h4.z, w0.z, a0); a0 = fmaf(h4.w, w0.w, a0);
            a1 = fmaf(h4.x, w1.x, a1); a1 = fmaf(h4.y, w1.y, a1);
            a1 = fmaf(h4.z, w1.z, a1); a1 = fmaf(h4.w, w1.w, a1);
            a2 = fmaf(h4.x, w2.x, a2); a2 = fmaf(h4.y, w2.y, a2);
            a2 = fmaf(h4.z, w2.z, a2); a2 = fmaf(h4.w, w2.w, a2);
            a3 = fmaf(h4.x, w3.x, a3); a3 = fmaf(h4.y, w3.y, a3);
            a3 = fmaf(h4.z, w3.z, a3); a3 = fmaf(h4.w, w3.w, a3);
        }
#pragma unroll
        for (int off = 16; off > 0; off >>= 1) {
            a0 += __shfl_down_sync(0xffffffffu, a0, off);
            a1 += __shfl_down_sync(0xffffffffu, a1, off);
            a2 += __shfl_down_sync(0xffffffffu, a2, off);
            a3 += __shfl_down_sync(0xffffffffu, a3, off);
        }

        if (lane == 0) {
            float zi = xp0 + a0;
            float zo = xp1 + a1;
            float zf = xp2 + a2;
            float zu = xp3 + a3;
            float ig = 1.f / (1.f + expf(-zi));
            float og = 1.f / (1.f + expf(-zo));
            float fg = 1.f / (1.f + expf(-zf));
            float ug = tanhf(zu);
            cval = fmaf(ig, ug, fg * cval);
            hval = og * tanhf(cval);
            g_h[(t & 1) ^ 1][j] = hval;   // write other buffer
            __threadfence();              // make visible before barrier release
        }
        grid_bar();
    }

    if (lane == 0) out[j] = hval;
}

// ---------------------------------------------------------------------------
extern "C" void kernel_launch(void* const* d_in, const int* in_sizes, int n_in,
                              void* d_out, int out_size)
{
    (void)in_sizes; (void)n_in; (void)out_size;
    const float* inputs = (const float*)d_in[0];   // (T,1,2048)
    const float* Wx     = (const float*)d_in[1];   // (8192,2048)
    const float* bx     = (const float*)d_in[2];   // (8192,)
    const float* Wh     = (const float*)d_in[3];   // (8192,2048)
    const float* bh     = (const float*)d_in[4];   // (8192,)
    float* out = (float*)d_out;                    // (1,2048)

    // Idempotent; safe to call every launch (not a stream op, capture-safe).
    cudaFuncSetAttribute(lstm_rec, cudaFuncAttributeMaxDynamicSharedMemorySize,
                         (int)REC_SMEM);

    dim3 ggrid(GDIM / BN, TSTEPS / BM);   // 64 x 64
    xproj_gemm<<<ggrid, 256>>>(inputs, Wx, bx, bh);

    lstm_rec<<<NCTA, NTH, REC_SMEM>>>(Wh, out);
}

// round 14
// speedup vs baseline: 1.2780x; 1.2780x over previous
#include <cuda_runtime.h>
#include <cuda_fp16.h>
#include <cstdint>

// Problem constants
#define TSTEPS 8192
#define MDIM   2048   // mem_dim
#define GDIM   8192   // 4*mem_dim
#define KDIM   2048   // in_dim

// Recurrence kernel config
#define NCTA   128            // co-resident CTAs (GB300 has 152 SMs)
#define NTH    512            // 16 warps; warp w owns hidden unit j = cta*16 + w
#define JPC    16             // MDIM / NCTA
// smem: h (2048 fp32 = 8KB) + 48 weight rows (gates 0..2) fp16 = 192KB
#define REC_SMEM (MDIM * 4 + 48 * MDIM * 2)   // 204800 B

// Scratch (static __device__ arrays: the sanctioned no-alloc workaround)
__device__ float  g_xproj[(size_t)TSTEPS * GDIM];   // 256 MB
__device__ __half g_wh16[(size_t)GDIM * MDIM];      // 32 MB fp16 copy of Wh
__device__ float  g_h[2][MDIM];                     // double-buffered hidden state
__device__ unsigned int          g_cnt;             // barrier arrival counter
__device__ volatile unsigned int g_gen;             // barrier generation (monotonic)

// ---------------------------------------------------------------------------
// f32x2 packed-FMA helpers (Blackwell dual fp32 FMA; ptxas never auto-emits)
// ---------------------------------------------------------------------------
typedef unsigned long long ull;

__device__ __forceinline__ ull dup2(float a) {
    ull r;
    asm("mov.b64 %0, {%1, %1};" : "=l"(r) : "f"(a));
    return r;
}
__device__ __forceinline__ void fma2(ull& acc, ull a, ull b) {
    asm("fma.rn.f32x2 %0, %1, %2, %0;" : "+l"(acc) : "l"(a), "l"(b));
}
__device__ __forceinline__ void unpack2(ull v, float& lo, float& hi) {
    asm("mov.b64 {%0, %1}, %2;" : "=f"(lo), "=f"(hi) : "l"(v));
}

// ---------------------------------------------------------------------------
// Kernel P: Wh fp32 -> fp16 (natural [G][K] layout)
// ---------------------------------------------------------------------------
__global__ void wh_to_half(const float* __restrict__ Wh)
{
    size_t i = ((size_t)blockIdx.x * blockDim.x + threadIdx.x) * 4;
    float4 v = *(const float4*)(Wh + i);
    __half2* dst = (__half2*)(g_wh16 + i);
    dst[0] = __floats2half2_rn(v.x, v.y);
    dst[1] = __floats2half2_rn(v.z, v.w);
}

// ---------------------------------------------------------------------------
// Kernel A: x_proj[t][g] = sum_k inputs[t][k] * Wx[g][k] + bx[g] + bh[g]
// 128x128x16 SGEMM, 256 threads, 8x8 microtile, packed f32x2 FMAs.
// ---------------------------------------------------------------------------
#define BM 128
#define BN 128
#define BK 16
#define TM 8
#define TN 8

__global__ __launch_bounds__(256, 2)
void xproj_gemm(const float* __restrict__ A,    // inputs [T][K]
                const float* __restrict__ B,    // Wx     [G][K]
                const float* __restrict__ bx,
                const float* __restrict__ bh)
{
    __shared__ __align__(16) float As[BK][BM];
    __shared__ __align__(16) float Bs[BK][BN];

    const int tid = threadIdx.x;
    const int tx  = tid & 15;    // N
    const int ty  = tid >> 4;    // M

    const float* Ab = A + (size_t)blockIdx.y * BM * KDIM;
    const float* Bb = B + (size_t)blockIdx.x * BN * KDIM;

    ull acc2[TM][TN / 2];
#pragma unroll
    for (int i = 0; i < TM; i++)
#pragma unroll
        for (int jp = 0; jp < TN / 2; jp++) acc2[i][jp] = 0ull;

    for (int k0 = 0; k0 < KDIM; k0 += BK) {
#pragma unroll
        for (int r = 0; r < 2; r++) {
            int i   = tid + r * 256;
            int row = i >> 2;
            int kq  = (i & 3) * 4;
            float4 va = *(const float4*)(Ab + (size_t)row * KDIM + k0 + kq);
            As[kq + 0][row] = va.x; As[kq + 1][row] = va.y;
            As[kq + 2][row] = va.z; As[kq + 3][row] = va.w;
            float4 vb = *(const float4*)(Bb + (size_t)row * KDIM + k0 + kq);
            Bs[kq + 0][row] = vb.x; Bs[kq + 1][row] = vb.y;
            Bs[kq + 2][row] = vb.z; Bs[kq + 3][row] = vb.w;
        }
        __syncthreads();

#pragma unroll
        for (int kk = 0; kk < BK; kk++) {
            const float4* pa = (const float4*)&As[kk][ty * TM];
            const ull*    pb = (const ull*)&Bs[kk][tx * TN];
            float4 a0 = pa[0], a1 = pa[1];
            ull bb0 = pb[0], bb1 = pb[1], bb2 = pb[2], bb3 = pb[3];
            ull ad[TM];
            ad[0] = dup2(a0.x); ad[1] = dup2(a0.y);
            ad[2] = dup2(a0.z); ad[3] = dup2(a0.w);
            ad[4] = dup2(a1.x); ad[5] = dup2(a1.y);
            ad[6] = dup2(a1.z); ad[7] = dup2(a1.w);
#pragma unroll
            for (int i = 0; i < TM; i++) {
                fma2(acc2[i][0], ad[i], bb0);
                fma2(acc2[i][1], ad[i], bb1);
                fma2(acc2[i][2], ad[i], bb2);
                fma2(acc2[i][3], ad[i], bb3);
            }
        }
        __syncthreads();
    }

    const int grow = blockIdx.y * BM + ty * TM;
    const int gcol = blockIdx.x * BN + tx * TN;
    float bias[TN];
#pragma unroll
    for (int j = 0; j < TN; j++) bias[j] = bx[gcol + j] + bh[gcol + j];

#pragma unroll
    for (int i = 0; i < TM; i++) {
        float v[TN];
#pragma unroll
        for (int jp = 0; jp < TN / 2; jp++)
            unpack2(acc2[i][jp], v[2 * jp], v[2 * jp + 1]);
        float4 o0, o1;
        o0.x = v[0] + bias[0]; o0.y = v[1] + bias[1];
        o0.z = v[2] + bias[2]; o0.w = v[3] + bias[3];
        o1.x = v[4] + bias[4]; o1.y = v[5] + bias[5];
        o1.z = v[6] + bias[6]; o1.w = v[7] + bias[7];
        float4* dst = (float4*)(g_xproj + (size_t)(grow + i) * GDIM + gcol);
        dst[0] = o0;
        dst[1] = o1;
    }
}

// ---------------------------------------------------------------------------
// Grid-wide barrier (all NCTA CTAs co-resident, 1 CTA/SM).
// ---------------------------------------------------------------------------
__device__ __forceinline__ void grid_bar()
{
    __syncthreads();
    if (threadIdx.x == 0) {
        unsigned gen = g_gen;           // read BEFORE arriving
        __threadfence();
        unsigned arrived = atomicAdd(&g_cnt, 1);
        if (arrived == NCTA - 1) {
            g_cnt = 0;
            __threadfence();
            g_gen = gen + 1;            // release
        } else {
            while (g_gen == gen) { __nanosleep(32); }
        }
        __threadfence();                // acquire
    }
    __syncthreads();
}

// ---------------------------------------------------------------------------
// Kernel B: persistent LSTM recurrence, Wh fully on-chip in fp16.
//   CTA c owns units [c*16, c*16+16); warp w owns unit j = c*16 + w.
//   Gates 0..2 rows (48/CTA) live in smem; gate 3 (u) row lives in 32
//   registers per thread. h snapshot in smem fp32. Zero weight traffic/step.
// ---------------------------------------------------------------------------
__global__ void __launch_bounds__(NTH, 1)
lstm_rec(float* __restrict__ out)
{
    extern __shared__ char smraw[];
    float*  h_s = (float*)smraw;                        // 2048 fp32
    __half* w_s = (__half*)(smraw + MDIM * 4);          // 48 rows x 2048 half

    const int tid  = threadIdx.x;
    const int lane = tid & 31;
    const int w    = tid >> 5;           // warp 0..15 == local unit
    const int cta  = blockIdx.x;
    const int j    = cta * JPC + w;      // global hidden unit

    // --- one-time: copy this warp's 3 smem rows (gates 0..2) ---
#pragma unroll
    for (int g = 0; g < 3; g++) {
        const uint4* src = (const uint4*)(g_wh16 + ((size_t)(g * MDIM + j)) * MDIM);
        uint4*       dst = (uint4*)(w_s + (size_t)(g * 16 + w) * MDIM);
#pragma unroll
        for (int r = 0; r < 8; r++)
            dst[lane + 32 * r] = src[lane + 32 * r];
    }

    // --- one-time: load this warp's u-gate row into registers ---
    // lane holds k = 4*(lane + 32*jj) .. +3 for jj = 0..15 (uint2 = 4 half)
    uint2 wreg[16];
    {
        const uint2* src = (const uint2*)(g_wh16 + ((size_t)(3 * MDIM + j)) * MDIM);
#pragma unroll
        for (int jj = 0; jj < 16; jj++)
            wreg[jj] = src[lane + 32 * jj];
    }

    // per-warp smem row bases (uint2 view, 1024 uint2 per row)
    const uint2* ws2 = (const uint2*)w_s;
    const uint2* r0 = ws2 + (size_t)(0 * 16 + w) * (MDIM / 4);
    const uint2* r1 = ws2 + (size_t)(1 * 16 + w) * (MDIM / 4);
    const uint2* r2 = ws2 + (size_t)(2 * 16 + w) * (MDIM / 4);

    if (lane == 0) g_h[0][j] = 0.f;
    float cval = 0.f, hval = 0.f;
    __threadfence();
    grid_bar();

    for (int t = 0; t < TSTEPS; t++) {
        // snapshot h_prev (other SMs wrote it -> bypass L1)
        {
            float4 hv = __ldcg(((const float4*)g_h[t & 1]) + tid);
            ((float4*)h_s)[tid] = hv;
        }
        __syncthreads();

        // prefetch x_proj (independent of h)
        float xp0 = 0.f, xp1 = 0.f, xp2 = 0.f, xp3 = 0.f;
        if (lane == 0) {
            const float* xr = g_xproj + (size_t)t * GDIM + j;
            xp0 = __ldcs(xr);
            xp1 = __ldcs(xr + MDIM);
            xp2 = __ldcs(xr + 2 * MDIM);
            xp3 = __ldcs(xr + 3 * MDIM);
        }

        float a0 = 0.f, a1 = 0.f, a2 = 0.f, a3 = 0.f;
#pragma unroll
        for (int jj = 0; jj < 16; jj++) {
            const int idx = lane + 32 * jj;
            float4 h4 = *((const float4*)h_s + idx);

            uint2 v0 = r0[idx];
            uint2 v1 = r1[idx];
            uint2 v2 = r2[idx];
            uint2 v3 = wreg[jj];

            float2 f0a = __half22float2(*(const __half2*)&v0.x);
            float2 f0b = __half22float2(*(const __half2*)&v0.y);
            float2 f1a = __half22float2(*(const __half2*)&v1.x);
            float2 f1b = __half22float2(*(const __half2*)&v1.y);
            float2 f2a = __half22float2(*(const __half2*)&v2.x);
            float2 f2b = __half22float2(*(const __half2*)&v2.y);
            float2 f3a = __half22float2(*(const __half2*)&v3.x);
            float2 f3b = __half22float2(*(const __half2*)&v3.y);

            a0 = fmaf(h4.x, f0a.x, a0); a0 = fmaf(h4.y, f0a.y, a0);
            a0 = fmaf(h4.z, f0b.x, a0); a0 = fmaf(h4.w, f0b.y, a0);
            a1 = fmaf(h4.x, f1a.x, a1); a1 = fmaf(h4.y, f1a.y, a1);
            a1 = fmaf(h4.z, f1b.x, a1); a1 = fmaf(h4.w, f1b.y, a1);
            a2 = fmaf(h4.x, f2a.x, a2); a2 = fmaf(h4.y, f2a.y, a2);
            a2 = fmaf(h4.z, f2b.x, a2); a2 = fmaf(h4.w, f2b.y, a2);
            a3 = fmaf(h4.x, f3a.x, a3); a3 = fmaf(h4.y, f3a.y, a3);
            a3 = fmaf(h4.z, f3b.x, a3); a3 = fmaf(h4.w, f3b.y, a3);
        }

#pragma unroll
        for (int off = 16; off > 0; off >>= 1) {
            a0 += __shfl_xor_sync(0xffffffffu, a0, off);
            a1 += __shfl_xor_sync(0xffffffffu, a1, off);
            a2 += __shfl_xor_sync(0xffffffffu, a2, off);
            a3 += __shfl_xor_sync(0xffffffffu, a3, off);
        }

        if (lane == 0) {
            float zi = xp0 + a0;
            float zo = xp1 + a1;
            float zf = xp2 + a2;
            float zu = xp3 + a3;
            float ig = 1.f / (1.f + __expf(-zi));
            float og = 1.f / (1.f + __expf(-zo));
            float fg = 1.f / (1.f + __expf(-zf));
            float ug = 2.f / (1.f + __expf(-2.f * zu)) - 1.f;   // tanh
            cval = fmaf(ig, ug, fg * cval);
            float tc = 2.f / (1.f + __expf(-2.f * cval)) - 1.f; // tanh(c)
            hval = og * tc;
            g_h[(t & 1) ^ 1][j] = hval;
            __threadfence();
        }
        grid_bar();
    }

    if (lane == 0) out[j] = hval;
}

// ---------------------------------------------------------------------------
extern "C" void kernel_launch(void* const* d_in, const int* in_sizes, int n_in,
                              void* d_out, int out_size)
{
    (void)in_sizes; (void)n_in; (void)out_size;
    const float* inputs = (const float*)d_in[0];   // (T,1,2048)
    const float* Wx     = (const float*)d_in[1];   // (8192,2048)
    const float* bx     = (const float*)d_in[2];   // (8192,)
    const float* Wh     = (const float*)d_in[3];   // (8192,2048)
    const float* bh     = (const float*)d_in[4];   // (8192,)
    float* out = (float*)d_out;                    // (1,2048)

    cudaFuncSetAttribute(lstm_rec, cudaFuncAttributeMaxDynamicSharedMemorySize,
                         (int)REC_SMEM);

    // Wh -> fp16 scratch (16.78M elems, 4 per thread)
    wh_to_half<<<(GDIM * (MDIM / 4)) / 256, 256>>>(Wh);

    dim3 ggrid(GDIM / BN, TSTEPS / BM);   // 64 x 64
    xproj_gemm<<<ggrid, 256>>>(inputs, Wx, bx, bh);

    lstm_rec<<<NCTA, NTH, REC_SMEM>>>(out);
}

// round 15
// speedup vs baseline: 1.6637x; 1.3019x over previous
#include <cuda_runtime.h>
#include <cuda_fp16.h>
#include <cstdint>

// Problem constants
#define TSTEPS 8192
#define MDIM   2048   // mem_dim
#define GDIM   8192   // 4*mem_dim
#define KDIM   2048   // in_dim

// Recurrence kernel config
#define NCTA   128            // co-resident CTAs (GB300 has 152 SMs)
#define NTH    512            // 16 warps; warp w owns hidden unit j = cta*16 + w
#define JPC    16             // MDIM / NCTA
// smem: h (2048 fp32 = 8KB) + 48 weight rows (gates 0..2) fp16 = 192KB
#define REC_SMEM (MDIM * 4 + 48 * MDIM * 2)   // 204800 B

// Scratch (static __device__ arrays: the sanctioned no-alloc workaround)
__device__ float  g_xproj[(size_t)TSTEPS * GDIM];   // 256 MB
__device__ __half g_wh16[(size_t)GDIM * MDIM];      // 32 MB fp16 copy of Wh
__device__ float  g_h[2][MDIM];                     // double-buffered hidden state
__device__ unsigned int          g_cnt;             // init-barrier arrival counter
__device__ volatile unsigned int g_gen;             // init-barrier generation (monotonic)
__device__ unsigned int          g_cnt2;            // per-step threshold counter

typedef unsigned long long ull;

// ---------------------------------------------------------------------------
// f32x2 packed-FMA helpers
// ---------------------------------------------------------------------------
__device__ __forceinline__ ull dup2(float a) {
    ull r;
    asm("mov.b64 %0, {%1, %1};" : "=l"(r) : "f"(a));
    return r;
}
__device__ __forceinline__ void fma2(ull& acc, ull a, ull b) {
    asm("fma.rn.f32x2 %0, %1, %2, %0;" : "+l"(acc) : "l"(a), "l"(b));
}
__device__ __forceinline__ void unpack2(ull v, float& lo, float& hi) {
    asm("mov.b64 {%0, %1}, %2;" : "=f"(lo), "=f"(hi) : "l"(v));
}

// 4 fp16 weights (uint2) * 4 fp32 h values (2 packed pairs) -> packed acc
__device__ __forceinline__ void gate_fma(ull& acc, uint2 v, ull h01, ull h23) {
    asm("{\n\t"
        ".reg .b16 ha, hb, hc, hd;\n\t"
        ".reg .f32 f0, f1, f2, f3;\n\t"
        ".reg .b64 p0, p1;\n\t"
        "mov.b32 {ha, hb}, %1;\n\t"
        "mov.b32 {hc, hd}, %2;\n\t"
        "cvt.f32.f16 f0, ha;\n\t"
        "cvt.f32.f16 f1, hb;\n\t"
        "cvt.f32.f16 f2, hc;\n\t"
        "cvt.f32.f16 f3, hd;\n\t"
        "mov.b64 p0, {f0, f1};\n\t"
        "mov.b64 p1, {f2, f3};\n\t"
        "fma.rn.f32x2 %0, %3, p0, %0;\n\t"
        "fma.rn.f32x2 %0, %4, p1, %0;\n\t"
        "}" : "+l"(acc) : "r"(v.x), "r"(v.y), "l"(h01), "l"(h23));
}

// ---------------------------------------------------------------------------
// Kernel P: Wh fp32 -> fp16 (natural [G][K] layout)
// ---------------------------------------------------------------------------
__global__ void wh_to_half(const float* __restrict__ Wh)
{
    size_t i = ((size_t)blockIdx.x * blockDim.x + threadIdx.x) * 4;
    float4 v = *(const float4*)(Wh + i);
    __half2* dst = (__half2*)(g_wh16 + i);
    dst[0] = __floats2half2_rn(v.x, v.y);
    dst[1] = __floats2half2_rn(v.z, v.w);
}

// ---------------------------------------------------------------------------
// Kernel A: x_proj = inputs @ Wx^T + bx + bh  (128x128x16 tiles, f32x2 FMAs)
// ---------------------------------------------------------------------------
#define BM 128
#define BN 128
#define BK 16
#define TM 8
#define TN 8

__global__ __launch_bounds__(256, 2)
void xproj_gemm(const float* __restrict__ A,
                const float* __restrict__ B,
                const float* __restrict__ bx,
                const float* __restrict__ bh)
{
    __shared__ __align__(16) float As[BK][BM];
    __shared__ __align__(16) float Bs[BK][BN];

    const int tid = threadIdx.x;
    const int tx  = tid & 15;
    const int ty  = tid >> 4;

    const float* Ab = A + (size_t)blockIdx.y * BM * KDIM;
    const float* Bb = B + (size_t)blockIdx.x * BN * KDIM;

    ull acc2[TM][TN / 2];
#pragma unroll
    for (int i = 0; i < TM; i++)
#pragma unroll
        for (int jp = 0; jp < TN / 2; jp++) acc2[i][jp] = 0ull;

    for (int k0 = 0; k0 < KDIM; k0 += BK) {
#pragma unroll
        for (int r = 0; r < 2; r++) {
            int i   = tid + r * 256;
            int row = i >> 2;
            int kq  = (i & 3) * 4;
            float4 va = *(const float4*)(Ab + (size_t)row * KDIM + k0 + kq);
            As[kq + 0][row] = va.x; As[kq + 1][row] = va.y;
            As[kq + 2][row] = va.z; As[kq + 3][row] = va.w;
            float4 vb = *(const float4*)(Bb + (size_t)row * KDIM + k0 + kq);
            Bs[kq + 0][row] = vb.x; Bs[kq + 1][row] = vb.y;
            Bs[kq + 2][row] = vb.z; Bs[kq + 3][row] = vb.w;
        }
        __syncthreads();

#pragma unroll
        for (int kk = 0; kk < BK; kk++) {
            const float4* pa = (const float4*)&As[kk][ty * TM];
            const ull*    pb = (const ull*)&Bs[kk][tx * TN];
            float4 a0 = pa[0], a1 = pa[1];
            ull bb0 = pb[0], bb1 = pb[1], bb2 = pb[2], bb3 = pb[3];
            ull ad[TM];
            ad[0] = dup2(a0.x); ad[1] = dup2(a0.y);
            ad[2] = dup2(a0.z); ad[3] = dup2(a0.w);
            ad[4] = dup2(a1.x); ad[5] = dup2(a1.y);
            ad[6] = dup2(a1.z); ad[7] = dup2(a1.w);
#pragma unroll
            for (int i = 0; i < TM; i++) {
                fma2(acc2[i][0], ad[i], bb0);
                fma2(acc2[i][1], ad[i], bb1);
                fma2(acc2[i][2], ad[i], bb2);
                fma2(acc2[i][3], ad[i], bb3);
            }
        }
        __syncthreads();
    }

    const int grow = blockIdx.y * BM + ty * TM;
    const int gcol = blockIdx.x * BN + tx * TN;
    float bias[TN];
#pragma unroll
    for (int j = 0; j < TN; j++) bias[j] = bx[gcol + j] + bh[gcol + j];

#pragma unroll
    for (int i = 0; i < TM; i++) {
        float v[TN];
#pragma unroll
        for (int jp = 0; jp < TN / 2; jp++)
            unpack2(acc2[i][jp], v[2 * jp], v[2 * jp + 1]);
        float4 o0, o1;
        o0.x = v[0] + bias[0]; o0.y = v[1] + bias[1];
        o0.z = v[2] + bias[2]; o0.w = v[3] + bias[3];
        o1.x = v[4] + bias[4]; o1.y = v[5] + bias[5];
        o1.z = v[6] + bias[6]; o1.w = v[7] + bias[7];
        float4* dst = (float4*)(g_xproj + (size_t)(grow + i) * GDIM + gcol);
        dst[0] = o0;
        dst[1] = o1;
    }
}

// ---------------------------------------------------------------------------
// Init barrier (gen-based; used ONCE per launch). Releaser resets g_cnt2,
// making the per-step threshold barrier exact on every graph replay.
// ---------------------------------------------------------------------------
__device__ __forceinline__ void init_bar()
{
    __syncthreads();
    if (threadIdx.x == 0) {
        unsigned gen = g_gen;
        __threadfence();
        unsigned arrived = atomicAdd(&g_cnt, 1);
        if (arrived == NCTA - 1) {
            g_cnt  = 0;
            g_cnt2 = 0;            // reset step counter for this launch
            __threadfence();
            g_gen = gen + 1;       // release
        } else {
            while (g_gen == gen) { }
        }
        __threadfence();           // acquire
    }
    __syncthreads();
}

// ---------------------------------------------------------------------------
// Kernel B: persistent LSTM recurrence, Wh fully on-chip in fp16.
// Per-step sync: one red.release.gpu.add per CTA + acquire-poll on threshold.
// ---------------------------------------------------------------------------
__global__ void __launch_bounds__(NTH, 1)
lstm_rec(float* __restrict__ out)
{
    extern __shared__ char smraw[];
    float*  h_s = (float*)smraw;                        // 2048 fp32
    __half* w_s = (__half*)(smraw + MDIM * 4);          // 48 rows x 2048 half

    const int tid  = threadIdx.x;
    const int lane = tid & 31;
    const int w    = tid >> 5;
    const int cta  = blockIdx.x;
    const int j    = cta * JPC + w;      // global hidden unit

    // one-time: gates 0..2 rows into smem
#pragma unroll
    for (int g = 0; g < 3; g++) {
        const uint4* src = (const uint4*)(g_wh16 + ((size_t)(g * MDIM + j)) * MDIM);
        uint4*       dst = (uint4*)(w_s + (size_t)(g * 16 + w) * MDIM);
#pragma unroll
        for (int r = 0; r < 8; r++)
            dst[lane + 32 * r] = src[lane + 32 * r];
    }

    // one-time: u-gate row into registers (uint2 = 4 fp16)
    uint2 wreg[16];
    {
        const uint2* src = (const uint2*)(g_wh16 + ((size_t)(3 * MDIM + j)) * MDIM);
#pragma unroll
        for (int jj = 0; jj < 16; jj++)
            wreg[jj] = src[lane + 32 * jj];
    }

    const uint2* ws2 = (const uint2*)w_s;
    const uint2* r0 = ws2 + (size_t)(0 * 16 + w) * (MDIM / 4);
    const uint2* r1 = ws2 + (size_t)(1 * 16 + w) * (MDIM / 4);
    const uint2* r2 = ws2 + (size_t)(2 * 16 + w) * (MDIM / 4);

    if (lane == 0) g_h[0][j] = 0.f;
    float cval = 0.f, hval = 0.f;
    __threadfence();
    init_bar();      // also resets g_cnt2 exactly once per launch

    for (int t = 0; t < TSTEPS; t++) {
        // snapshot h_prev into smem (other SMs wrote it -> bypass L1)
        {
            float4 hv = __ldcg(((const float4*)g_h[t & 1]) + tid);
            ((float4*)h_s)[tid] = hv;
        }
        __syncthreads();

        // prefetch x_proj for this step (independent of h; overlaps dot loop)
        float xp0 = 0.f, xp1 = 0.f, xp2 = 0.f, xp3 = 0.f;
        if (lane == 0) {
            const float* xr = g_xproj + (size_t)t * GDIM + j;
            xp0 = __ldcs(xr);
            xp1 = __ldcs(xr + MDIM);
            xp2 = __ldcs(xr + 2 * MDIM);
            xp3 = __ldcs(xr + 3 * MDIM);
        }

        ull A0 = 0ull, A1 = 0ull, A2 = 0ull, A3 = 0ull;
#pragma unroll
        for (int jj = 0; jj < 16; jj++) {
            const int idx = lane + 32 * jj;
            ulonglong2 hv = ((const ulonglong2*)h_s)[idx];   // packed (h0,h1),(h2,h3)
            gate_fma(A0, r0[idx],   hv.x, hv.y);
            gate_fma(A1, r1[idx],   hv.x, hv.y);
            gate_fma(A2, r2[idx],   hv.x, hv.y);
            gate_fma(A3, wreg[jj],  hv.x, hv.y);
        }
        float a0, a1, a2, a3;
        {
            float lo, hi;
            unpack2(A0, lo, hi); a0 = lo + hi;
            unpack2(A1, lo, hi); a1 = lo + hi;
            unpack2(A2, lo, hi); a2 = lo + hi;
            unpack2(A3, lo, hi); a3 = lo + hi;
        }
#pragma unroll
        for (int off = 16; off > 0; off >>= 1) {
            a0 += __shfl_xor_sync(0xffffffffu, a0, off);
            a1 += __shfl_xor_sync(0xffffffffu, a1, off);
            a2 += __shfl_xor_sync(0xffffffffu, a2, off);
            a3 += __shfl_xor_sync(0xffffffffu, a3, off);
        }

        if (lane == 0) {
            float zi = xp0 + a0;
            float zo = xp1 + a1;
            float zf = xp2 + a2;
            float zu = xp3 + a3;
            float ig = 1.f / (1.f + __expf(-zi));
            float og = 1.f / (1.f + __expf(-zo));
            float fg = 1.f / (1.f + __expf(-zf));
            float ug = 2.f / (1.f + __expf(-2.f * zu)) - 1.f;
            cval = fmaf(ig, ug, fg * cval);
            float tc = 2.f / (1.f + __expf(-2.f * cval)) - 1.f;
            hval = og * tc;
            g_h[(t & 1) ^ 1][j] = hval;
        }

        // ---- fast grid barrier: release-add + acquire threshold poll ----
        __syncthreads();                       // all warps' h stores done (CTA order)
        if (tid == 0) {
            asm volatile("red.release.gpu.add.u32 [%0], %1;"
                         :: "l"(&g_cnt2), "r"(1u) : "memory");
            const unsigned target = (unsigned)(t + 1) * NCTA;
            unsigned v;
            do {
                asm volatile("ld.acquire.gpu.u32 %0, [%1];"
                             : "=r"(v) : "l"(&g_cnt2) : "memory");
            } while (v < target);
        }
        __syncthreads();                       // propagate pass to whole CTA
    }

    if (lane == 0) out[j] = hval;
}

// ---------------------------------------------------------------------------
extern "C" void kernel_launch(void* const* d_in, const int* in_sizes, int n_in,
                              void* d_out, int out_size)
{
    (void)in_sizes; (void)n_in; (void)out_size;
    const float* inputs = (const float*)d_in[0];   // (T,1,2048)
    const float* Wx     = (const float*)d_in[1];   // (8192,2048)
    const float* bx     = (const float*)d_in[2];   // (8192,)
    const float* Wh     = (const float*)d_in[3];   // (8192,2048)
    const float* bh     = (const float*)d_in[4];   // (8192,)
    float* out = (float*)d_out;                    // (1,2048)

    cudaFuncSetAttribute(lstm_rec, cudaFuncAttributeMaxDynamicSharedMemorySize,
                         (int)REC_SMEM);

    wh_to_half<<<(GDIM * (MDIM / 4)) / 256, 256>>>(Wh);

    dim3 ggrid(GDIM / BN, TSTEPS / BM);   // 64 x 64
    xproj_gemm<<<ggrid, 256>>>(inputs, Wx, bx, bh);

    lstm_rec<<<NCTA, NTH, REC_SMEM>>>(out);
}

// round 16
// speedup vs baseline: 1.8618x; 1.1190x over previous
#include <cuda_runtime.h>
#include <cuda_fp16.h>
#include <cstdint>

// Problem constants
#define TSTEPS 8192
#define MDIM   2048   // mem_dim
#define GDIM   8192   // 4*mem_dim
#define KDIM   2048   // in_dim

// Recurrence kernel config
#define NCTA   128            // co-resident CTAs (GB300 has 152 SMs)
#define NTH    512            // 16 warps; warp w owns hidden unit j = cta*16 + w
#define JPC    16             // MDIM / NCTA
// smem: h fp16 (2048*2 = 4KB) + 48 weight rows (gates 0..2) fp16 = 192KB
#define REC_SMEM (MDIM * 2 + 48 * MDIM * 2)   // 200704 B

// Scratch (static __device__ arrays: the sanctioned no-alloc workaround)
__device__ float  g_xproj[(size_t)TSTEPS * GDIM];   // 256 MB
__device__ __half g_wh16[(size_t)GDIM * MDIM];      // 32 MB fp16 copy of Wh
__device__ float  g_h[2][MDIM];                     // double-buffered hidden state
__device__ unsigned int          g_cnt;             // init-barrier arrival counter
__device__ volatile unsigned int g_gen;             // init-barrier generation (monotonic)
__device__ unsigned int          g_cnt2;            // per-step threshold counter

typedef unsigned long long ull;

// ---------------------------------------------------------------------------
// f32x2 packed-FMA helpers (GEMM)
// ---------------------------------------------------------------------------
__device__ __forceinline__ ull dup2(float a) {
    ull r;
    asm("mov.b64 %0, {%1, %1};" : "=l"(r) : "f"(a));
    return r;
}
__device__ __forceinline__ void fma2(ull& acc, ull a, ull b) {
    asm("fma.rn.f32x2 %0, %1, %2, %0;" : "+l"(acc) : "l"(a), "l"(b));
}
__device__ __forceinline__ void unpack2(ull v, float& lo, float& hi) {
    asm("mov.b64 {%0, %1}, %2;" : "=f"(lo), "=f"(hi) : "l"(v));
}

// ---------------------------------------------------------------------------
// Mixed-precision dot: 8 fp16 weights (uint4) * 8 fp16 h (uint4) -> f32 acc.
// fma.rn.f32.f16 = f16*f16 with exact f32 accumulate (sm_100+ mixed FMA).
// The mov.b32 {lo,hi} splits fold into HFMA half-lane selectors in SASS.
// ---------------------------------------------------------------------------
__device__ __forceinline__ void gate8(float& acc, uint4 w, uint4 h) {
    asm("{\n\t"
        ".reg .b16 a0,a1,a2,a3,a4,a5,a6,a7;\n\t"
        ".reg .b16 b0,b1,b2,b3,b4,b5,b6,b7;\n\t"
        "mov.b32 {a0,a1}, %1;\n\t"
        "mov.b32 {a2,a3}, %2;\n\t"
        "mov.b32 {a4,a5}, %3;\n\t"
        "mov.b32 {a6,a7}, %4;\n\t"
        "mov.b32 {b0,b1}, %5;\n\t"
        "mov.b32 {b2,b3}, %6;\n\t"
        "mov.b32 {b4,b5}, %7;\n\t"
        "mov.b32 {b6,b7}, %8;\n\t"
        "fma.rn.f32.f16 %0, a0, b0, %0;\n\t"
        "fma.rn.f32.f16 %0, a1, b1, %0;\n\t"
        "fma.rn.f32.f16 %0, a2, b2, %0;\n\t"
        "fma.rn.f32.f16 %0, a3, b3, %0;\n\t"
        "fma.rn.f32.f16 %0, a4, b4, %0;\n\t"
        "fma.rn.f32.f16 %0, a5, b5, %0;\n\t"
        "fma.rn.f32.f16 %0, a6, b6, %0;\n\t"
        "fma.rn.f32.f16 %0, a7, b7, %0;\n\t"
        "}"
        : "+f"(acc)
        : "r"(w.x), "r"(w.y), "r"(w.z), "r"(w.w),
          "r"(h.x), "r"(h.y), "r"(h.z), "r"(h.w));
}

// ---------------------------------------------------------------------------
// Kernel P: Wh fp32 -> fp16 (natural [G][K] layout)
// ---------------------------------------------------------------------------
__global__ void wh_to_half(const float* __restrict__ Wh)
{
    size_t i = ((size_t)blockIdx.x * blockDim.x + threadIdx.x) * 4;
    float4 v = *(const float4*)(Wh + i);
    __half2* dst = (__half2*)(g_wh16 + i);
    dst[0] = __floats2half2_rn(v.x, v.y);
    dst[1] = __floats2half2_rn(v.z, v.w);
}

// ---------------------------------------------------------------------------
// Kernel A: x_proj = inputs @ Wx^T + bx + bh  (128x128x16 tiles, f32x2 FMAs)
// ---------------------------------------------------------------------------
#define BM 128
#define BN 128
#define BK 16
#define TM 8
#define TN 8

__global__ __launch_bounds__(256, 2)
void xproj_gemm(const float* __restrict__ A,
                const float* __restrict__ B,
                const float* __restrict__ bx,
                const float* __restrict__ bh)
{
    __shared__ __align__(16) float As[BK][BM];
    __shared__ __align__(16) float Bs[BK][BN];

    const int tid = threadIdx.x;
    const int tx  = tid & 15;
    const int ty  = tid >> 4;

    const float* Ab = A + (size_t)blockIdx.y * BM * KDIM;
    const float* Bb = B + (size_t)blockIdx.x * BN * KDIM;

    ull acc2[TM][TN / 2];
#pragma unroll
    for (int i = 0; i < TM; i++)
#pragma unroll
        for (int jp = 0; jp < TN / 2; jp++) acc2[i][jp] = 0ull;

    for (int k0 = 0; k0 < KDIM; k0 += BK) {
#pragma unroll
        for (int r = 0; r < 2; r++) {
            int i   = tid + r * 256;
            int row = i >> 2;
            int kq  = (i & 3) * 4;
            float4 va = *(const float4*)(Ab + (size_t)row * KDIM + k0 + kq);
            As[kq + 0][row] = va.x; As[kq + 1][row] = va.y;
            As[kq + 2][row] = va.z; As[kq + 3][row] = va.w;
            float4 vb = *(const float4*)(Bb + (size_t)row * KDIM + k0 + kq);
            Bs[kq + 0][row] = vb.x; Bs[kq + 1][row] = vb.y;
            Bs[kq + 2][row] = vb.z; Bs[kq + 3][row] = vb.w;
        }
        __syncthreads();

#pragma unroll
        for (int kk = 0; kk < BK; kk++) {
            const float4* pa = (const float4*)&As[kk][ty * TM];
            const ull*    pb = (const ull*)&Bs[kk][tx * TN];
            float4 a0 = pa[0], a1 = pa[1];
            ull bb0 = pb[0], bb1 = pb[1], bb2 = pb[2], bb3 = pb[3];
            ull ad[TM];
            ad[0] = dup2(a0.x); ad[1] = dup2(a0.y);
            ad[2] = dup2(a0.z); ad[3] = dup2(a0.w);
            ad[4] = dup2(a1.x); ad[5] = dup2(a1.y);
            ad[6] = dup2(a1.z); ad[7] = dup2(a1.w);
#pragma unroll
            for (int i = 0; i < TM; i++) {
                fma2(acc2[i][0], ad[i], bb0);
                fma2(acc2[i][1], ad[i], bb1);
                fma2(acc2[i][2], ad[i], bb2);
                fma2(acc2[i][3], ad[i], bb3);
            }
        }
        __syncthreads();
    }

    const int grow = blockIdx.y * BM + ty * TM;
    const int gcol = blockIdx.x * BN + tx * TN;
    float bias[TN];
#pragma unroll
    for (int j = 0; j < TN; j++) bias[j] = bx[gcol + j] + bh[gcol + j];

#pragma unroll
    for (int i = 0; i < TM; i++) {
        float v[TN];
#pragma unroll
        for (int jp = 0; jp < TN / 2; jp++)
            unpack2(acc2[i][jp], v[2 * jp], v[2 * jp + 1]);
        float4 o0, o1;
        o0.x = v[0] + bias[0]; o0.y = v[1] + bias[1];
        o0.z = v[2] + bias[2]; o0.w = v[3] + bias[3];
        o1.x = v[4] + bias[4]; o1.y = v[5] + bias[5];
        o1.z = v[6] + bias[6]; o1.w = v[7] + bias[7];
        float4* dst = (float4*)(g_xproj + (size_t)(grow + i) * GDIM + gcol);
        dst[0] = o0;
        dst[1] = o1;
    }
}

// ---------------------------------------------------------------------------
// Init barrier (gen-based; used ONCE per launch). Releaser resets g_cnt2,
// making the per-step threshold barrier exact on every graph replay.
// ---------------------------------------------------------------------------
__device__ __forceinline__ void init_bar()
{
    __syncthreads();
    if (threadIdx.x == 0) {
        unsigned gen = g_gen;
        __threadfence();
        unsigned arrived = atomicAdd(&g_cnt, 1);
        if (arrived == NCTA - 1) {
            g_cnt  = 0;
            g_cnt2 = 0;            // reset step counter for this launch
            __threadfence();
            g_gen = gen + 1;       // release
        } else {
            while (g_gen == gen) { }
        }
        __threadfence();           // acquire
    }
    __syncthreads();
}

// ---------------------------------------------------------------------------
// Kernel B: persistent LSTM recurrence, Wh fully on-chip in fp16.
// Mixed-precision HFMA (f16*f16 -> f32 acc); h snapshot converted to fp16
// once per step. One release-add + acquire threshold-poll barrier per step.
// ---------------------------------------------------------------------------
__global__ void __launch_bounds__(NTH, 1)
lstm_rec(float* __restrict__ out)
{
    extern __shared__ char smraw[];
    __half* h16 = (__half*)smraw;                       // 2048 fp16
    __half* w_s = (__half*)(smraw + MDIM * 2);          // 48 rows x 2048 fp16

    const int tid  = threadIdx.x;
    const int lane = tid & 31;
    const int w    = tid >> 5;
    const int cta  = blockIdx.x;
    const int j    = cta * JPC + w;      // global hidden unit

    // one-time: gates 0..2 rows into smem
#pragma unroll
    for (int g = 0; g < 3; g++) {
        const uint4* src = (const uint4*)(g_wh16 + ((size_t)(g * MDIM + j)) * MDIM);
        uint4*       dst = (uint4*)(w_s + (size_t)(g * 16 + w) * MDIM);
#pragma unroll
        for (int r = 0; r < 8; r++)
            dst[lane + 32 * r] = src[lane + 32 * r];
    }

    // one-time: u-gate row into registers (uint4 = 8 fp16)
    uint4 wreg[8];
    {
        const uint4* src = (const uint4*)(g_wh16 + ((size_t)(3 * MDIM + j)) * MDIM);
#pragma unroll
        for (int ii = 0; ii < 8; ii++)
            wreg[ii] = src[lane + 32 * ii];
    }

    const uint4* ws4 = (const uint4*)w_s;
    const uint4* r0 = ws4 + (size_t)(0 * 16 + w) * (MDIM / 8);
    const uint4* r1 = ws4 + (size_t)(1 * 16 + w) * (MDIM / 8);
    const uint4* r2 = ws4 + (size_t)(2 * 16 + w) * (MDIM / 8);

    if (lane == 0) g_h[0][j] = 0.f;
    float cval = 0.f, hval = 0.f;
    __threadfence();
    init_bar();      // also resets g_cnt2 exactly once per launch

    for (int t = 0; t < TSTEPS; t++) {
        // snapshot h_prev -> fp16 smem (other SMs wrote it -> bypass L1)
        {
            float4 hv = __ldcg(((const float4*)g_h[t & 1]) + tid);
            __half2 p0 = __floats2half2_rn(hv.x, hv.y);
            __half2 p1 = __floats2half2_rn(hv.z, hv.w);
            uint2 u;
            u.x = *(unsigned*)&p0;
            u.y = *(unsigned*)&p1;
            ((uint2*)h16)[tid] = u;
        }
        __syncthreads();

        // prefetch x_proj for this step (independent of h; overlaps dot loop)
        float xp0 = 0.f, xp1 = 0.f, xp2 = 0.f, xp3 = 0.f;
        if (lane == 0) {
            const float* xr = g_xproj + (size_t)t * GDIM + j;
            xp0 = __ldcs(xr);
            xp1 = __ldcs(xr + MDIM);
            xp2 = __ldcs(xr + 2 * MDIM);
            xp3 = __ldcs(xr + 3 * MDIM);
        }

        float a0 = 0.f, a1 = 0.f, a2 = 0.f, a3 = 0.f;
#pragma unroll
        for (int ii = 0; ii < 8; ii++) {
            const int idx = lane + 32 * ii;
            uint4 hv = ((const uint4*)h16)[idx];   // 8 fp16 h values
            gate8(a0, r0[idx],   hv);
            gate8(a1, r1[idx],   hv);
            gate8(a2, r2[idx],   hv);
            gate8(a3, wreg[ii],  hv);
        }

#pragma unroll
        for (int off = 16; off > 0; off >>= 1) {
            a0 += __shfl_xor_sync(0xffffffffu, a0, off);
            a1 += __shfl_xor_sync(0xffffffffu, a1, off);
            a2 += __shfl_xor_sync(0xffffffffu, a2, off);
            a3 += __shfl_xor_sync(0xffffffffu, a3, off);
        }

        if (lane == 0) {
            float zi = xp0 + a0;
            float zo = xp1 + a1;
            float zf = xp2 + a2;
            float zu = xp3 + a3;
            float ig = 1.f / (1.f + __expf(-zi));
            float og = 1.f / (1.f + __expf(-zo));
            float fg = 1.f / (1.f + __expf(-zf));
            float ug = 2.f / (1.f + __expf(-2.f * zu)) - 1.f;
            cval = fmaf(ig, ug, fg * cval);
            float tc = 2.f / (1.f + __expf(-2.f * cval)) - 1.f;
            hval = og * tc;
            g_h[(t & 1) ^ 1][j] = hval;
        }

        // ---- fast grid barrier: release-add + acquire threshold poll ----
        __syncthreads();                       // all warps' h stores done
        if (tid == 0) {
            asm volatile("red.release.gpu.add.u32 [%0], %1;"
                         :: "l"(&g_cnt2), "r"(1u) : "memory");
            const unsigned target = (unsigned)(t + 1) * NCTA;
            unsigned v;
            do {
                asm volatile("ld.acquire.gpu.u32 %0, [%1];"
                             : "=r"(v) : "l"(&g_cnt2) : "memory");
            } while (v < target);
        }
        __syncthreads();                       // propagate pass to whole CTA
    }

    if (lane == 0) out[j] = hval;
}

// ---------------------------------------------------------------------------
extern "C" void kernel_launch(void* const* d_in, const int* in_sizes, int n_in,
                              void* d_out, int out_size)
{
    (void)in_sizes; (void)n_in; (void)out_size;
    const float* inputs = (const float*)d_in[0];   // (T,1,2048)
    const float* Wx     = (const float*)d_in[1];   // (8192,2048)
    const float* bx     = (const float*)d_in[2];   // (8192,)
    const float* Wh     = (const float*)d_in[3];   // (8192,2048)
    const float* bh     = (const float*)d_in[4];   // (8192,)
    float* out = (float*)d_out;                    // (1,2048)

    cudaFuncSetAttribute(lstm_rec, cudaFuncAttributeMaxDynamicSharedMemorySize,
                         (int)REC_SMEM);

    wh_to_half<<<(GDIM * (MDIM / 4)) / 256, 256>>>(Wh);

    dim3 ggrid(GDIM / BN, TSTEPS / BM);   // 64 x 64
    xproj_gemm<<<ggrid, 256>>>(inputs, Wx, bx, bh);

    lstm_rec<<<NCTA, NTH, REC_SMEM>>>(out);
}